// round 1
// baseline (speedup 1.0000x reference)
#include <cuda_runtime.h>
#include <math.h>

#define TSTEPS 512
#define BATCH  64
#define DH     1024
#define NBLK   128
#define TOTAL  (TSTEPS * BATCH * DH)   // 33554432 elements per output copy

// ---- scratch (static device arrays; no allocation) ----
__device__ __align__(16) float g_P[TOTAL];            // 134 MB: X@Wx + b, all timesteps
__device__ __align__(16) float g_S[BATCH * DH];       // current state
__device__ __align__(16) float g_part[8 * BATCH * DH];// split-K partials (2 MB, L2-resident)
__device__ unsigned g_cnt   = 0;
__device__ unsigned g_phase = 0;

// ---------------------------------------------------------------------------
// Grid-wide barrier (sense via monotonically increasing phase). All NBLK
// blocks are guaranteed co-resident (NBLK=128 <= 148 SMs, 1 small CTA/SM).
// Count returns to 0 after every barrier, so state is consistent across
// graph replays.
// ---------------------------------------------------------------------------
__device__ __forceinline__ void grid_bar()
{
    __syncthreads();
    if (threadIdx.x == 0) {
        __threadfence();
        unsigned ph = *((volatile unsigned*)&g_phase);
        unsigned old = atomicAdd(&g_cnt, 1u);
        if (old == NBLK - 1) {
            g_cnt = 0;
            __threadfence();
            atomicExch(&g_phase, ph + 1u);
        } else {
            while (*((volatile unsigned*)&g_phase) == ph) { }
        }
        __threadfence();
    }
    __syncthreads();
}

// ---------------------------------------------------------------------------
// Phase 1: g_P[t*64+b][j] = sum_k X[t*64+b][k] * Wx[k][j] + bias[j]
// M=32768, N=1024, K=1024. 128x128 block tile, BK=8, 8x8 per thread.
// ---------------------------------------------------------------------------
__global__ void __launch_bounds__(256, 2)
gemm_xwx(const float* __restrict__ X, const float* __restrict__ Wx,
         const float* __restrict__ bias)
{
    __shared__ __align__(16) float As[128][8];
    __shared__ __align__(16) float Bs[8][128];

    const int tid  = threadIdx.x;
    const int row0 = blockIdx.x << 7;
    const int col0 = blockIdx.y << 7;
    const int ty   = tid >> 4;        // 0..15
    const int tx   = tid & 15;        // 0..15

    float acc[8][8];
#pragma unroll
    for (int i = 0; i < 8; i++)
#pragma unroll
        for (int j = 0; j < 8; j++) acc[i][j] = 0.0f;

    const int ar = tid >> 1, aq = (tid & 1) << 2;       // A tile: 128 rows x 8 k
    const int bk = tid >> 5, bc = (tid & 31) << 2;      // B tile: 8 k x 128 cols

    for (int k0 = 0; k0 < 1024; k0 += 8) {
        float4 av = *(const float4*)&X [(size_t)(row0 + ar) * 1024 + k0 + aq];
        float4 bv = *(const float4*)&Wx[(size_t)(k0 + bk) * 1024 + col0 + bc];
        *(float4*)&As[ar][aq] = av;
        *(float4*)&Bs[bk][bc] = bv;
        __syncthreads();
#pragma unroll
        for (int kk = 0; kk < 8; kk++) {
            float a[8], b[8];
#pragma unroll
            for (int i = 0; i < 8; i++) a[i] = As[ty * 8 + i][kk];
#pragma unroll
            for (int j = 0; j < 8; j++) b[j] = Bs[kk][tx * 8 + j];
#pragma unroll
            for (int i = 0; i < 8; i++)
#pragma unroll
                for (int j = 0; j < 8; j++)
                    acc[i][j] += a[i] * b[j];
        }
        __syncthreads();
    }

    float bb[8];
#pragma unroll
    for (int j = 0; j < 8; j++) bb[j] = bias[col0 + tx * 8 + j];
#pragma unroll
    for (int i = 0; i < 8; i++) {
        size_t ro = (size_t)(row0 + ty * 8 + i) * 1024 + col0 + tx * 8;
        *(float4*)&g_P[ro]     = make_float4(acc[i][0] + bb[0], acc[i][1] + bb[1],
                                             acc[i][2] + bb[2], acc[i][3] + bb[3]);
        *(float4*)&g_P[ro + 4] = make_float4(acc[i][4] + bb[4], acc[i][5] + bb[5],
                                             acc[i][6] + bb[6], acc[i][7] + bb[7]);
    }
}

// ---------------------------------------------------------------------------
// Phase 2: persistent recurrence. Per step:
//   A: 128 blocks = 16 col-tiles (64 cols) x 8 K-splits (128 k each):
//      partial Z tile [64 x 64] -> g_part.   (grid barrier)
//   B: block b finalizes 8 columns: sum partials + P[t], tanh, per-column
//      batch-norm (fully block-local), write out + g_S.   (grid barrier)
// Cross-SM data (g_S, g_part) read via __ldcg (L2) to avoid stale L1.
// ---------------------------------------------------------------------------
__global__ void __launch_bounds__(256, 1)
rnn_recur(const float* __restrict__ Wh, const float* __restrict__ state0,
          float* __restrict__ out)
{
    __shared__ __align__(16) float Ssh[64 * 64];   // [row][k]  16 KB
    __shared__ __align__(16) float Wsh[64 * 64];   // [k][col]  16 KB
    __shared__ float hsh[512];

    const int tid = threadIdx.x;
    const int bid = blockIdx.x;
    const int jt  = bid & 15;        // column tile (64 cols)
    const int ks  = bid >> 4;        // K split (128 k)
    const int k0  = ks << 7;
    const int j0  = jt << 6;
    const int jb0 = bid << 3;        // 8 columns owned in phase B

    // init state from input (state_tensor[0] == zeros, but honor the input)
    {
        int g = bid * 256 + tid;               // 32768 threads, 16384 float4s
        if (g < (BATCH * DH) / 4)
            ((float4*)g_S)[g] = ((const float4*)state0)[g];
    }
    const int r0 = (tid >> 4) << 2;            // 0..60
    const int c0 = (tid & 15) << 2;            // 0..60
    grid_bar();

    for (int t = 0; t < TSTEPS; t++) {
        // ---------------- A: partial GEMM ----------------
        float acc[4][4];
#pragma unroll
        for (int i = 0; i < 4; i++)
#pragma unroll
            for (int j = 0; j < 4; j++) acc[i][j] = 0.0f;

        for (int half = 0; half < 2; half++) {
            const int kb = k0 + (half << 6);
#pragma unroll
            for (int it = 0; it < 4; it++) {   // S chunk: 64 rows x 64 k
                int idx = tid + (it << 8);
                int r = idx >> 4, q = (idx & 15) << 2;
                float4 v = __ldcg((const float4*)&g_S[(r << 10) + kb + q]);
                *(float4*)&Ssh[(r << 6) + q] = v;
            }
#pragma unroll
            for (int it = 0; it < 4; it++) {   // Wh chunk: 64 k x 64 cols
                int idx = tid + (it << 8);
                int kk = idx >> 4, c = (idx & 15) << 2;
                float4 v = *(const float4*)&Wh[(size_t)(kb + kk) * 1024 + j0 + c];
                *(float4*)&Wsh[(kk << 6) + c] = v;
            }
            __syncthreads();
#pragma unroll 4
            for (int kk = 0; kk < 64; kk += 4) {
                float4 a[4], bf[4];
#pragma unroll
                for (int i = 0; i < 4; i++)
                    a[i] = *(const float4*)&Ssh[((r0 + i) << 6) + kk];
#pragma unroll
                for (int m = 0; m < 4; m++)
                    bf[m] = *(const float4*)&Wsh[((kk + m) << 6) + c0];
#pragma unroll
                for (int i = 0; i < 4; i++) {
                    const float* ai = (const float*)&a[i];
#pragma unroll
                    for (int m = 0; m < 4; m++) {
                        const float av = ai[m];
                        const float* bm = (const float*)&bf[m];
#pragma unroll
                        for (int j = 0; j < 4; j++)
                            acc[i][j] += av * bm[j];
                    }
                }
            }
            __syncthreads();
        }
        {
            float* pp = &g_part[ks << 16];
#pragma unroll
            for (int i = 0; i < 4; i++)
                *(float4*)&pp[((r0 + i) << 10) + j0 + c0] =
                    make_float4(acc[i][0], acc[i][1], acc[i][2], acc[i][3]);
        }
        __threadfence();
        grid_bar();

        // ---------------- B: reduce + tanh + batchnorm ----------------
#pragma unroll
        for (int u = 0; u < 2; u++) {
            int e = tid + (u << 8);
            int r = e >> 3, c = e & 7;
            int j = jb0 + c;
            float v = g_P[((size_t)t * 64 + r) * 1024 + j];
#pragma unroll
            for (int s = 0; s < 8; s++)
                v += __ldcg(&g_part[(s << 16) + (r << 10) + j]);
            hsh[e] = tanhf(v);
        }
        __syncthreads();
        {
            int w = tid >> 5, lane = tid & 31;       // warp w owns column w
            float h1 = hsh[(lane << 3) + w];
            float h2 = hsh[((lane + 32) << 3) + w];
            float ssum = h1 + h2;
#pragma unroll
            for (int off = 16; off > 0; off >>= 1)
                ssum += __shfl_xor_sync(0xffffffffu, ssum, off);
            float mu = ssum * (1.0f / 64.0f);
            float d1 = h1 - mu, d2 = h2 - mu;
            float q2 = d1 * d1 + d2 * d2;
#pragma unroll
            for (int off = 16; off > 0; off >>= 1)
                q2 += __shfl_xor_sync(0xffffffffu, q2, off);
            float inv = rsqrtf(q2 * (1.0f / 64.0f) + 1e-5f);
            hsh[(lane << 3) + w]        = d1 * inv;
            hsh[((lane + 32) << 3) + w] = d2 * inv;
        }
        __syncthreads();
#pragma unroll
        for (int u = 0; u < 2; u++) {
            int e = tid + (u << 8);
            int r = e >> 3, c = e & 7;
            int j = jb0 + c;
            float val = hsh[e];
            size_t o = ((size_t)t * 64 + r) * 1024 + j;
            out[o]                 = val;
            out[o + (size_t)TOTAL] = val;   // reference returns (outputs, outputs)
            g_S[(r << 10) + j]     = val;
        }
        __threadfence();
        grid_bar();
    }
}

// ---------------------------------------------------------------------------
extern "C" void kernel_launch(void* const* d_in, const int* in_sizes, int n_in,
                              void* d_out, int out_size)
{
    const float* X    = (const float*)d_in[0];   // [512,64,1024]
    const float* S0   = (const float*)d_in[1];   // [1,64,1024]
    const float* Wx   = (const float*)d_in[2];   // [1024,1024]
    const float* Wh   = (const float*)d_in[3];   // [1024,1024]
    const float* bias = (const float*)d_in[4];   // [1024]
    float* out = (float*)d_out;

    dim3 g1(256, 8);                 // 32768/128 x 1024/128
    gemm_xwx<<<g1, 256>>>(X, Wx, bias);
    rnn_recur<<<NBLK, 256>>>(Wh, S0, out);
}

// round 6
// speedup vs baseline: 1.7340x; 1.7340x over previous
#include <cuda_runtime.h>
#include <cuda_bf16.h>
#include <stdint.h>
#include <math.h>

#define TSTEPS 512
#define TOTAL  (TSTEPS * 64 * 1024)      // 33554432 floats per output copy
#define NBLK2  64                        // phase-2 persistent CTAs
#define PLANE_X 33554432u                // 32768*1024 halves per X plane

// ---------------- static device scratch (no allocation) ----------------
__device__ __align__(16) float          g_P[TOTAL];                 // X@Wx+b (fp32)
__device__ __align__(16) __nv_bfloat16  g_Xb[2u * PLANE_X];         // [plane][row 32768][k 1024]
__device__ __align__(16) __nv_bfloat16  g_Wxb[2u * 1024 * 1024];    // [plane][n][k] = Wx[k][n]
__device__ __align__(16) __nv_bfloat16  g_Whb[2u * 1024 * 1024];    // [plane][n][k] = Wh[k][n]
__device__ __align__(16) __nv_bfloat16  g_Sb[2][2 * 65536];         // ping-pong [plane][64 r][1024 k]
__device__ unsigned g_cnt = 0, g_phase = 0;

#define SWZ(o) ((o) ^ (((o) >> 3) & 0x70))

// ---------------- helpers ----------------
__device__ __forceinline__ uint32_t smem_u32(const void* p) {
    uint32_t a;
    asm("{ .reg .u64 t; cvta.to.shared.u64 t, %1; cvt.u32.u64 %0, t; }" : "=r"(a) : "l"(p));
    return a;
}
__device__ __forceinline__ void ldsm4(uint32_t* r, uint32_t addr) {
    asm volatile("ldmatrix.sync.aligned.m8n8.x4.shared.b16 {%0,%1,%2,%3}, [%4];"
                 : "=r"(r[0]), "=r"(r[1]), "=r"(r[2]), "=r"(r[3]) : "r"(addr));
}
__device__ __forceinline__ void mma_bf16(float* c, const uint32_t* a, const uint32_t* b) {
    asm volatile(
        "mma.sync.aligned.m16n8k16.row.col.f32.bf16.bf16.f32 "
        "{%0,%1,%2,%3}, {%4,%5,%6,%7}, {%8,%9}, {%0,%1,%2,%3};"
        : "+f"(c[0]), "+f"(c[1]), "+f"(c[2]), "+f"(c[3])
        : "r"(a[0]), "r"(a[1]), "r"(a[2]), "r"(a[3]), "r"(b[0]), "r"(b[1]));
}
__device__ __forceinline__ void cp16(uint32_t dst, const void* src) {
    asm volatile("cp.async.cg.shared.global [%0], [%1], 16;" :: "r"(dst), "l"(src) : "memory");
}
__device__ __forceinline__ void cp_commit() { asm volatile("cp.async.commit_group;" ::: "memory"); }
template <int N> __device__ __forceinline__ void cp_wait() {
    asm volatile("cp.async.wait_group %0;" :: "n"(N) : "memory");
}

// ---------------- grid barrier (phase 2, 64 CTAs, all co-resident) ----------------
__device__ __forceinline__ void grid_bar() {
    __syncthreads();
    if (threadIdx.x == 0) {
        __threadfence();
        unsigned ph = *((volatile unsigned*)&g_phase);
        unsigned old = atomicAdd(&g_cnt, 1u);
        if (old == NBLK2 - 1) {
            g_cnt = 0;
            __threadfence();
            atomicExch(&g_phase, ph + 1u);
        } else {
            while (*((volatile unsigned*)&g_phase) == ph) { }
        }
        __threadfence();
    }
    __syncthreads();
}

// ---------------- conversion kernels ----------------
// W [1024 k x 1024 n] f32 -> out[plane][n][k] bf16 (transposed, hi/lo)
__global__ void conv_w(const float* __restrict__ W, int which)
{
    __nv_bfloat16* out = which ? g_Whb : g_Wxb;
    __shared__ float sm[64][65];
    const int n0 = blockIdx.x << 6, k0 = blockIdx.y << 6;
    const int tid = threadIdx.x;
#pragma unroll
    for (int it = 0; it < 16; it++) {
        int e = it * 256 + tid;
        int kk = e >> 6, nn = e & 63;
        sm[kk][nn] = W[(size_t)(k0 + kk) * 1024 + n0 + nn];
    }
    __syncthreads();
#pragma unroll
    for (int it = 0; it < 16; it++) {
        int e = it * 256 + tid;
        int nn = e >> 6, kk = e & 63;
        float v = sm[kk][nn];
        __nv_bfloat16 hi = __float2bfloat16(v);
        __nv_bfloat16 lo = __float2bfloat16(v - __bfloat162float(hi));
        size_t o = (size_t)(n0 + nn) * 1024 + k0 + kk;
        out[o]            = hi;
        out[o + 1048576u] = lo;
    }
}

// X [32768 rows x 1024] f32 -> g_Xb [plane][row][k] bf16
__global__ void conv_x(const float* __restrict__ X)
{
    int v = blockIdx.x * 256 + threadIdx.x;
#pragma unroll
    for (int i = 0; i < 8; i++) {
        int f4 = v + i * 1048576;                  // 8388608 float4 total
        const float4 x = ((const float4*)X)[f4];
        size_t e0 = (size_t)f4 << 2;               // element offset (row*1024 + k)
        float xs[4] = {x.x, x.y, x.z, x.w};
        unsigned short hs[4], ls[4];
#pragma unroll
        for (int q = 0; q < 4; q++) {
            __nv_bfloat16 hv = __float2bfloat16(xs[q]);
            __nv_bfloat16 lv = __float2bfloat16(xs[q] - __bfloat162float(hv));
            hs[q] = __bfloat16_as_ushort(hv); ls[q] = __bfloat16_as_ushort(lv);
        }
        *(ushort4*)(g_Xb + e0)           = make_ushort4(hs[0], hs[1], hs[2], hs[3]);
        *(ushort4*)(g_Xb + e0 + PLANE_X) = make_ushort4(ls[0], ls[1], ls[2], ls[3]);
    }
}

// ---------------- phase 1: P = X@Wx + b (mma.sync bf16, 3-term) ----------------
// grid (8 n-tiles, 256 m-tiles), 256 thr (8 warps, 16 rows each). Tile 128x128, k-slab 64.
// smem: 2 stages x { A [2p][128r][128B], B [2p][128n][128B] } = 2 x 64KB
#define P1_SMEM 131072

#define P1_ISSUE(kt) do {                                                              \
    _Pragma("unroll")                                                                  \
    for (int i = 0; i < 8; i++) {                                                      \
        int id = i * 256 + tid;                                                        \
        int ku = id & 7, r = (id >> 3) & 127, p = id >> 10;                            \
        uint32_t off = (uint32_t)((((kt) & 1) << 16) + (p << 14)                       \
                       + SWZ((uint32_t)(r * 128 + ku * 16)));                          \
        cp16(su + off,         g_Xb  + (size_t)p * PLANE_X                             \
             + (size_t)(m0 + r) * 1024 + (kt) * 64 + ku * 8);                          \
        cp16(su + off + 32768, g_Wxb + (size_t)p * 1048576                             \
             + (size_t)(col0 + r) * 1024 + (kt) * 64 + ku * 8);                        \
    }                                                                                  \
    cp_commit();                                                                       \
} while (0)

__global__ void __launch_bounds__(256, 1)
gemm_p1(const float* __restrict__ bias)
{
    extern __shared__ __align__(1024) char dyn[];
    const uint32_t su = smem_u32(dyn);
    const int tid = threadIdx.x, wid = tid >> 5, lane = tid & 31;
    const int col0 = blockIdx.x << 7, m0 = blockIdx.y << 7;

    const int laneR = lane & 7, idq = lane >> 3;
    const int rowA = laneR + ((idq & 1) << 3), k8A = (idq >> 1) << 3;
    const int nB   = laneR + ((idq >> 1) << 3), k8B = (idq & 1) << 3;
    uint32_t swzA[4], swzB[4];
#pragma unroll
    for (int kc = 0; kc < 4; kc++) {
        swzA[kc] = SWZ((uint32_t)(rowA * 128 + (kc * 16 + k8A) * 2));
        swzB[kc] = SWZ((uint32_t)(nB   * 128 + (kc * 16 + k8B) * 2));
    }

    float c[16][4];
#pragma unroll
    for (int q = 0; q < 16; q++)
#pragma unroll
        for (int j = 0; j < 4; j++) c[q][j] = 0.0f;

    P1_ISSUE(0);
    for (int kt = 0; kt < 16; kt++) {
        if (kt < 15) { P1_ISSUE(kt + 1); cp_wait<1>(); } else { cp_wait<0>(); }
        __syncthreads();
        const uint32_t Ab = su + ((kt & 1) << 16) + (wid << 11);
        const uint32_t Bb = su + ((kt & 1) << 16) + 32768;
#pragma unroll
        for (int kc = 0; kc < 4; kc++) {
            uint32_t ah[4], al[4], bb[32];
            ldsm4(ah, Ab + swzA[kc]);
            ldsm4(al, Ab + 16384 + swzA[kc]);
#pragma unroll
            for (int q = 0; q < 8; q++) ldsm4(&bb[q * 4], Bb + q * 2048 + swzB[kc]);
#pragma unroll
            for (int q = 0; q < 8; q++) {
                mma_bf16(c[2 * q],     ah, &bb[q * 4]);
                mma_bf16(c[2 * q + 1], ah, &bb[q * 4 + 2]);
            }
#pragma unroll
            for (int q = 0; q < 8; q++) {
                mma_bf16(c[2 * q],     al, &bb[q * 4]);
                mma_bf16(c[2 * q + 1], al, &bb[q * 4 + 2]);
            }
#pragma unroll
            for (int q = 0; q < 8; q++) ldsm4(&bb[q * 4], Bb + 16384 + q * 2048 + swzB[kc]);
#pragma unroll
            for (int q = 0; q < 8; q++) {
                mma_bf16(c[2 * q],     ah, &bb[q * 4]);
                mma_bf16(c[2 * q + 1], ah, &bb[q * 4 + 2]);
            }
        }
        __syncthreads();
    }

    const int r0 = m0 + (wid << 4) + (lane >> 2);
#pragma unroll
    for (int nb = 0; nb < 16; nb++) {
        int colp = col0 + nb * 8 + ((lane & 3) << 1);
        float2 bb = *(const float2*)&bias[colp];
        *(float2*)&g_P[(size_t)r0 * 1024 + colp]       = make_float2(c[nb][0] + bb.x, c[nb][1] + bb.y);
        *(float2*)&g_P[(size_t)(r0 + 8) * 1024 + colp] = make_float2(c[nb][2] + bb.x, c[nb][3] + bb.y);
    }
}

// ---------------- phase 2: persistent recurrence ----------------
// 64 CTAs x 128 thr (4 warps, 16 rows each). CTA owns 16 columns.
// smem: stages 2 x 32KB (A: [2p][4w][2ks][16r][128B]) @0, Wh [2p][16s][16n][128B] @65536,
//       epilogue staging @131072.
#define P2_SMEM 136576

#define P2_ISSUE(ss) do {                                                              \
    _Pragma("unroll")                                                                  \
    for (int i = 0; i < 16; i++) {                                                     \
        int id = i * 128 + tid;                                                        \
        int ku = id & 15, r = (id >> 4) & 63, p = id >> 10;                            \
        uint32_t off = (uint32_t)((((ss) & 1) << 15)                                   \
                       + (((p * 4 + (r >> 4)) * 2 + (ku >> 3)) << 11)                  \
                       + SWZ((uint32_t)((r & 15) * 128 + (ku & 7) * 16)));             \
        cp16(su + off, Sb + (size_t)p * 65536 + (size_t)r * 1024 + (ss) * 128 + ku * 8); \
    }                                                                                  \
    cp_commit();                                                                       \
} while (0)

__global__ void __launch_bounds__(128, 1)
rnn_p2(const float* __restrict__ state0, float* __restrict__ out)
{
    extern __shared__ __align__(1024) char dyn[];
    const uint32_t su = smem_u32(dyn);
    const int tid = threadIdx.x, wid = tid >> 5, lane = tid & 31;
    const int n0 = blockIdx.x << 4;

    const int laneR = lane & 7, idq = lane >> 3;
    const int rowA = laneR + ((idq & 1) << 3), k8A = (idq >> 1) << 3;
    const int nB   = laneR + ((idq >> 1) << 3), k8B = (idq & 1) << 3;
    uint32_t swzA[4], swzB[4];
#pragma unroll
    for (int kc = 0; kc < 4; kc++) {
        swzA[kc] = SWZ((uint32_t)(rowA * 128 + (kc * 16 + k8A) * 2));
        swzB[kc] = SWZ((uint32_t)(nB   * 128 + (kc * 16 + k8B) * 2));
    }

    // resident Wh slice: [2p][16 s64][16 n][128B]
#pragma unroll 4
    for (int i = 0; i < 32; i++) {
        int id = i * 128 + tid;
        int ku = id & 127, n = (id >> 7) & 15, p = id >> 11;
        uint4 v = *(const uint4*)(g_Whb + (size_t)p * 1048576 + (size_t)(n0 + n) * 1024 + ku * 8);
        uint32_t off = 65536u + (uint32_t)(((p * 16 + (ku >> 3)) << 11)
                       + SWZ((uint32_t)(n * 128 + (ku & 7) * 16)));
        *(uint4*)(dyn + off) = v;
    }
    // init ping state from state0
    {
        int id = blockIdx.x * 128 + tid;
#pragma unroll
        for (int i = 0; i < 2; i++) {
            int f4 = id + i * 8192;                // 16384 float4
            float4 x = ((const float4*)state0)[f4];
            size_t e0 = (size_t)f4 << 2;
            float xs[4] = {x.x, x.y, x.z, x.w};
            unsigned short hs[4], ls[4];
#pragma unroll
            for (int q = 0; q < 4; q++) {
                __nv_bfloat16 hv = __float2bfloat16(xs[q]);
                __nv_bfloat16 lv = __float2bfloat16(xs[q] - __bfloat162float(hv));
                hs[q] = __bfloat16_as_ushort(hv); ls[q] = __bfloat16_as_ushort(lv);
            }
            *(ushort4*)(&g_Sb[0][e0])         = make_ushort4(hs[0], hs[1], hs[2], hs[3]);
            *(ushort4*)(&g_Sb[0][e0 + 65536]) = make_ushort4(ls[0], ls[1], ls[2], ls[3]);
        }
    }
    __threadfence();
    grid_bar();

    float* stg  = (float*)(dyn + 131072);          // [64][17]
    float* psum = stg + 64 * 17;                   // [8][16]
    float* psq  = psum + 128;                      // [8][16]
    float* cmu  = psq + 128;                       // [16]
    float* cinv = cmu + 16;                        // [16]
    const int j = tid & 15, hg = tid >> 4;

    for (int t = 0; t < TSTEPS; t++) {
        const __nv_bfloat16* Sb = g_Sb[t & 1];
        float c0[4] = {0, 0, 0, 0}, c1[4] = {0, 0, 0, 0};

        P2_ISSUE(0);
        for (int s = 0; s < 8; s++) {
            if (s < 7) { P2_ISSUE(s + 1); cp_wait<1>(); } else { cp_wait<0>(); }
            __syncthreads();
#pragma unroll
            for (int kc = 0; kc < 8; kc++) {
                uint32_t ah[4], al[4], bh[4], bl[4];
                uint32_t Ab = su + ((s & 1) << 15) + (wid << 12) + ((kc >> 2) << 11);
                uint32_t Bb = su + 65536 + ((s * 2 + (kc >> 2)) << 11);
                ldsm4(ah, Ab + swzA[kc & 3]);
                ldsm4(al, Ab + 16384 + swzA[kc & 3]);
                ldsm4(bh, Bb + swzB[kc & 3]);
                ldsm4(bl, Bb + 32768 + swzB[kc & 3]);
                mma_bf16(c0, ah, bh); mma_bf16(c1, ah, bh + 2);
                mma_bf16(c0, al, bh); mma_bf16(c1, al, bh + 2);
                mma_bf16(c0, ah, bl); mma_bf16(c1, ah, bl + 2);
            }
            __syncthreads();
        }

        // ---- epilogue: stage C, +P, tanh, per-column BN (block-local) ----
        {
            int rr = (wid << 4) + (lane >> 2);
            int cc = (lane & 3) << 1;
            stg[rr * 17 + cc]           = c0[0];
            stg[rr * 17 + cc + 1]       = c0[1];
            stg[(rr + 8) * 17 + cc]     = c0[2];
            stg[(rr + 8) * 17 + cc + 1] = c0[3];
            stg[rr * 17 + 8 + cc]           = c1[0];
            stg[rr * 17 + 8 + cc + 1]       = c1[1];
            stg[(rr + 8) * 17 + 8 + cc]     = c1[2];
            stg[(rr + 8) * 17 + 8 + cc + 1] = c1[3];
        }
        __syncthreads();

        float hv[8], ps = 0.0f, pq = 0.0f;
        const float* Pt = g_P + (size_t)t * 65536 + n0 + j;
#pragma unroll
        for (int i = 0; i < 8; i++) {
            int r = hg * 8 + i;
            float z = stg[r * 17 + j] + __ldg(&Pt[(size_t)r * 1024]);
            float h = tanhf(z);
            hv[i] = h; ps += h; pq += h * h;
        }
        psum[hg * 16 + j] = ps;
        psq[hg * 16 + j]  = pq;
        __syncthreads();
        if (tid < 16) {
            float s = 0.0f, q = 0.0f;
#pragma unroll
            for (int g2 = 0; g2 < 8; g2++) { s += psum[g2 * 16 + tid]; q += psq[g2 * 16 + tid]; }
            float mu  = s * (1.0f / 64.0f);
            float var = q * (1.0f / 64.0f) - mu * mu;
            cmu[tid]  = mu;
            cinv[tid] = rsqrtf(var + 1e-5f);
        }
        __syncthreads();
        {
            float mu = cmu[j], inv = cinv[j];
            __nv_bfloat16* Sn = g_Sb[(t + 1) & 1];
#pragma unroll
            for (int i = 0; i < 8; i++) {
                int r = hg * 8 + i;
                float sv = (hv[i] - mu) * inv;
                size_t o = ((size_t)t * 64 + r) * 1024 + n0 + j;
                out[o]                 = sv;
                out[o + (size_t)TOTAL] = sv;
                __nv_bfloat16 hb = __float2bfloat16(sv);
                __nv_bfloat16 lb = __float2bfloat16(sv - __bfloat162float(hb));
                Sn[(size_t)r * 1024 + n0 + j]         = hb;
                Sn[65536 + (size_t)r * 1024 + n0 + j] = lb;
            }
        }
        __threadfence();
        grid_bar();
    }
}

// ---------------------------------------------------------------------------
extern "C" void kernel_launch(void* const* d_in, const int* in_sizes, int n_in,
                              void* d_out, int out_size)
{
    const float* X    = (const float*)d_in[0];   // [512,64,1024]
    const float* S0   = (const float*)d_in[1];   // [1,64,1024]
    const float* Wx   = (const float*)d_in[2];   // [1024,1024]
    const float* Wh   = (const float*)d_in[3];   // [1024,1024]
    const float* bias = (const float*)d_in[4];   // [1024]
    float* out = (float*)d_out;

    cudaFuncSetAttribute(gemm_p1, cudaFuncAttributeMaxDynamicSharedMemorySize, P1_SMEM);
    cudaFuncSetAttribute(rnn_p2,  cudaFuncAttributeMaxDynamicSharedMemorySize, P2_SMEM);

    conv_w<<<dim3(16, 16), 256>>>(Wx, 0);
    conv_w<<<dim3(16, 16), 256>>>(Wh, 1);
    conv_x<<<4096, 256>>>(X);
    gemm_p1<<<dim3(8, 256), 256, P1_SMEM>>>(bias);
    rnn_p2<<<NBLK2, 128, P2_SMEM>>>(S0, out);
}